// round 16
// baseline (speedup 1.0000x reference)
#include <cuda_runtime.h>
#include <cstdint>

// Fixed shapes: pred/target = [4, 8192, 3] fp32
#define NB        4
#define NPTS      8192
#define THREADS   128
#define OCC       8
#define IPT       8                    // pred points per lane
#define JT        64                   // targets per tile
#define TILES     (NPTS / JT)          // 128 tiles per combo
#define NCOMBO    (NB * 8)             // 32 (b, ich) combos
#define GRID      (148 * OCC)          // 1184 CTAs: uniform 8/SM, 37 per combo
#define INF_BITS  0x7f800000

// Static device scratch.
__device__ float4       g_ppk[NB * NPTS];   // packed pred: (x,y,z,h)
__device__ float4       g_qpk[NB * NPTS];   // packed tgt:  (x,y,z,h)
__device__ int          g_rmin[NB * NPTS];  // int-ordered fp mins (>=0)
__device__ int          g_cmin[NB * NPTS];
__device__ unsigned int g_next[NCOMBO];     // per-combo tile queues
__device__ unsigned int g_done;

// Pack points and reset mins/queues.  32768 threads.
__global__ void chamfer_init_kernel(const float* __restrict__ pred,
                                    const float* __restrict__ tgt) {
    int idx = blockIdx.x * blockDim.x + threadIdx.x;   // 0 .. NB*NPTS-1
    float x = pred[3 * idx], y = pred[3 * idx + 1], z = pred[3 * idx + 2];
    g_ppk[idx] = make_float4(x, y, z, 0.5f * fmaf(x, x, fmaf(y, y, z * z)));
    x = tgt[3 * idx]; y = tgt[3 * idx + 1]; z = tgt[3 * idx + 2];
    g_qpk[idx] = make_float4(x, y, z, 0.5f * fmaf(x, x, fmaf(y, y, z * z)));
    g_rmin[idx] = INF_BITS;
    g_cmin[idx] = INF_BITS;
    if (idx < NCOMBO) g_next[idx] = 0u;
    if (idx == 0) g_done = 0u;
}

// Queue-balanced symmetric cross kernel, one barrier per tile.
//   s = h_q - p.q  (3 FFMA, negated-p source modifiers, q.w = +h_q)
//   rows: min(s) (+h_p at flush);  cols: t = h_p + s (FFMA-imm), 8-tree,
//   systolic SHFL ride (1 SHFL per 256 pairs).
__global__ void __launch_bounds__(THREADS, OCC)
chamfer_cross_kernel(float* __restrict__ out) {
    __shared__ float4       sq[2][2][64];    // double tile buffer, dup halves
    __shared__ float        scol[2][4][JT];  // double-buffered col mins
    __shared__ unsigned int s_draw[2];       // parity-alternating draw slots
    __shared__ int          s_last;
    __shared__ float        s_red[THREADS];

    const int combo = blockIdx.x & (NCOMBO - 1);
    const int b     = combo >> 3;
    const int ich   = combo & 7;
    const int tid   = threadIdx.x;
    const int w     = tid >> 5;
    const int lane  = tid & 31;

    const float4* Qp = &g_qpk[b * NPTS];
    int* grow = &g_rmin[b * NPTS];
    int* gcol = &g_cmin[b * NPTS];

    // Staging map: 128 threads <-> 128 duplicated slots.
    const int sh = tid >> 6;               // half
    const int sm = tid & 63;               // slot within half
    const int sj = (sh << 5) + (sm & 31);  // tile-local j this thread stages

    // Register-resident pred points (fixed for whole kernel).
    const int ib = ich * 1024 + w * 256 + lane * IPT;
    const float4* Pp = &g_ppk[b * NPTS + ib];
    float px[IPT], py[IPT], pz[IPT], hp[IPT], smin[IPT];
#pragma unroll
    for (int k = 0; k < IPT; k++) {
        float4 p = Pp[k];
        px[k] = p.x; py[k] = p.y; pz[k] = p.z; hp[k] = p.w;
        smin[k] = __int_as_float(INF_BITS);
    }

    // ---- Prologue: draw cur, nxt, nn; stage cur; prefetch nxt.
    if (tid == 0) s_draw[0] = atomicAdd(&g_next[combo], 1u);
    __syncthreads();
    unsigned int cur = s_draw[0];
    if (cur < TILES) sq[0][sh][sm] = Qp[cur * JT + sj];
    if (tid == 0) s_draw[1] = atomicAdd(&g_next[combo], 1u);
    __syncthreads();
    unsigned int nxt = s_draw[1];
    float4 qreg = make_float4(0.f, 0.f, 0.f, 0.f);
    if (nxt < TILES) qreg = Qp[nxt * JT + sj];
    if (tid == 0)
        s_draw[0] = (nxt < TILES) ? atomicAdd(&g_next[combo], 1u) : (unsigned)TILES;
    __syncthreads();   // buf0 staged; s_draw[0] (first nn) visible

    int pc = 0;
    while (cur < TILES) {
        // nn drawn last iteration (or prologue); visible after the barrier.
        unsigned int nn = s_draw[pc];
        // Stage tile nxt into the free buffer; prefetch tile nn.
        if (nxt < TILES) sq[pc ^ 1][sh][sm] = qreg;
        if (nn < TILES) qreg = Qp[nn * JT + sj];
        if (tid == 0)
            s_draw[pc ^ 1] = (nn < TILES) ? atomicAdd(&g_next[combo], 1u)
                                          : (unsigned)TILES;

        // ---- 64 systolic steps on buffer pc; cm rides one SHFL per step.
#pragma unroll
        for (int h = 0; h < 2; h++) {
            const float4* qp = &sq[pc][h][lane];
            float cm = __int_as_float(INF_BITS);
#pragma unroll 8
            for (int n = 0; n < 32; n++) {
                float4 q = qp[n];                    // LDS.128, ptr bump only
                float tm;
#pragma unroll
                for (int kk = 0; kk < IPT; kk += 2) {
                    float s0 = fmaf(-pz[kk],     q.z, fmaf(-py[kk],     q.y, fmaf(-px[kk],     q.x, q.w)));
                    float s1 = fmaf(-pz[kk + 1], q.z, fmaf(-py[kk + 1], q.y, fmaf(-px[kk + 1], q.x, q.w)));
                    smin[kk]     = fminf(smin[kk],     s0);
                    smin[kk + 1] = fminf(smin[kk + 1], s1);
                    float t0 = fmaf(s0, 1.0f, hp[kk]);     // t = hp + s (FFMA-imm)
                    float t1 = fmaf(s1, 1.0f, hp[kk + 1]);
                    float tp = fminf(t0, t1);
                    tm = (kk == 0) ? tp : fminf(tm, tp);
                }
                cm = fminf(cm, tm);
                cm = __shfl_sync(0xffffffffu, cm, lane + 1);
            }
            scol[pc][w][h * 32 + lane] = cm;
        }

        // Single barrier: STS(nxt) + s_draw visible; scol[pc] complete.
        __syncthreads();

        // Col combine for tile cur (overlaps next tile's compute).
        if (tid < JT) {
            float m = fminf(fminf(scol[pc][0][tid], scol[pc][1][tid]),
                            fminf(scol[pc][2][tid], scol[pc][3][tid]));
            atomicMin(&gcol[cur * JT + tid], __float_as_int(m));
        }

        cur = nxt; nxt = nn; pc ^= 1;
    }

    // Row flush once per CTA (add hp back here).
#pragma unroll
    for (int k = 0; k < IPT; k++)
        atomicMin(&grow[ib + k], __float_as_int(hp[k] + smin[k]));

    // Last CTA reduces everything to the scalar output.
    __threadfence();
    if (tid == 0) s_last = (atomicAdd(&g_done, 1u) == GRID - 1);
    __syncthreads();
    if (!s_last) return;
    __threadfence();

    float sum = 0.0f;
    for (int i = tid; i < NB * NPTS; i += THREADS)
        sum += __int_as_float(g_rmin[i]) + __int_as_float(g_cmin[i]);
    s_red[tid] = sum;
    __syncthreads();
    for (int o = THREADS / 2; o; o >>= 1) {
        if (tid < o) s_red[tid] += s_red[tid + o];
        __syncthreads();
    }
    // values are dist^2/2 -> x2; mean over NB batches and NPTS points.
    if (tid == 0)
        *out = s_red[0] * (2.0f / ((float)NB * (float)NPTS));
}

extern "C" void kernel_launch(void* const* d_in, const int* in_sizes, int n_in,
                              void* d_out, int out_size) {
    const float* pred = (const float*)d_in[0];
    const float* tgt  = (const float*)d_in[1];
    float* out = (float*)d_out;
    (void)in_sizes; (void)n_in; (void)out_size;

    chamfer_init_kernel<<<(NB * NPTS) / 256, 256>>>(pred, tgt);
    chamfer_cross_kernel<<<GRID, THREADS>>>(out);
}

// round 17
// speedup vs baseline: 1.0511x; 1.0511x over previous
#include <cuda_runtime.h>
#include <cstdint>

// Fixed shapes: pred/target = [4, 8192, 3] fp32
#define NB        4
#define NPTS      8192
#define THREADS   128
#define OCC       5
#define IPT       16                   // pred points per lane
#define I_PER_CTA 2048                 // 4 warps * 32 lanes * 16
#define ICH       4                    // 8192 / 2048
#define JT        64                   // targets per tile
#define TILES     (NPTS / JT)          // 128 tiles per combo
#define NCOMBO    (NB * ICH)           // 16 (b, ich) combos
#define GRID      (148 * OCC)          // 740 CTAs: 5/SM, ~46 per combo
#define INF_BITS  0x7f800000

// Static device scratch.
__device__ float4       g_ppk[NB * NPTS];   // packed pred: (x,y,z,h)
__device__ float4       g_qpk[NB * NPTS];   // packed tgt:  (x,y,z,h)
__device__ int          g_rmin[NB * NPTS];  // int-ordered fp mins (>=0)
__device__ int          g_cmin[NB * NPTS];
__device__ unsigned int g_next[NCOMBO];     // per-combo tile queues
__device__ unsigned int g_done;

// Pack points and reset mins/queues.  32768 threads.
__global__ void chamfer_init_kernel(const float* __restrict__ pred,
                                    const float* __restrict__ tgt) {
    int idx = blockIdx.x * blockDim.x + threadIdx.x;   // 0 .. NB*NPTS-1
    float x = pred[3 * idx], y = pred[3 * idx + 1], z = pred[3 * idx + 2];
    g_ppk[idx] = make_float4(x, y, z, 0.5f * fmaf(x, x, fmaf(y, y, z * z)));
    x = tgt[3 * idx]; y = tgt[3 * idx + 1]; z = tgt[3 * idx + 2];
    g_qpk[idx] = make_float4(x, y, z, 0.5f * fmaf(x, x, fmaf(y, y, z * z)));
    g_rmin[idx] = INF_BITS;
    g_cmin[idx] = INF_BITS;
    if (idx < NCOMBO) g_next[idx] = 0u;
    if (idx == 0) g_done = 0u;
}

// R12 skeleton with IPT=16. Each (i,j) computed once:
//   s = h_q - p.q  (3 FFMA, negated-p source modifiers, q.w = +h_q)
//   rows: min(s) (+h_p at flush);  cols: t = h_p + s (FFMA-imm), 16-tree,
//   systolic SHFL ride (1 SHFL per 512 pairs).
__global__ void __launch_bounds__(THREADS, OCC)
chamfer_cross_kernel(float* __restrict__ out) {
    // Duplicated tile halves: sq[h][m] = q-tile element h*32 + (m & 31)
    __shared__ float4       sq[2][63];
    __shared__ float        scol[4][JT];
    __shared__ unsigned int s_tile;
    __shared__ int          s_last;
    __shared__ float        s_red[THREADS];

    const int combo = blockIdx.x & (NCOMBO - 1);
    const int b     = combo >> 2;
    const int ich   = combo & 3;
    const int tid   = threadIdx.x;
    const int w     = tid >> 5;
    const int lane  = tid & 31;

    const float4* Qp = &g_qpk[b * NPTS];
    int* grow = &g_rmin[b * NPTS];
    int* gcol = &g_cmin[b * NPTS];

    // Register-resident pred points (fixed for whole kernel).
    const int ib = ich * I_PER_CTA + w * (32 * IPT) + lane * IPT;
    const float4* Pp = &g_ppk[b * NPTS + ib];
    float px[IPT], py[IPT], pz[IPT], hp[IPT], smin[IPT];
#pragma unroll
    for (int k = 0; k < IPT; k++) {
        float4 p = Pp[k];
        px[k] = p.x; py[k] = p.y; pz[k] = p.z; hp[k] = p.w;
        smin[k] = __int_as_float(INF_BITS);
    }

    for (;;) {
        if (tid == 0) s_tile = atomicAdd(&g_next[combo], 1u);
        __syncthreads();                       // also protects sq/scol reuse
        const unsigned int jch = s_tile;
        if (jch >= TILES) break;

        // Stage this j-tile into duplicated halves (packed float4 load).
        if (tid < JT) {
            float4 v = Qp[jch * JT + tid];
            int h = tid >> 5, m = tid & 31;
            sq[h][m] = v;
            if (m < 31) sq[h][32 + m] = v;
        }
        __syncthreads();

        // Systolic: lane reads sq[h][lane+n] (linear, conflict-free); the
        // col-min rides one SHFL per step and lands back on its home lane.
#pragma unroll
        for (int h = 0; h < 2; h++) {
            const float4* qp = &sq[h][lane];
            float cm = __int_as_float(INF_BITS);
#pragma unroll 4
            for (int n = 0; n < 32; n++) {
                float4 q = qp[n];                    // LDS.128, ptr bump only
                float tmA, tmB;
#pragma unroll
                for (int kk = 0; kk < 8; kk += 2) {
                    float s0 = fmaf(-pz[kk],     q.z, fmaf(-py[kk],     q.y, fmaf(-px[kk],     q.x, q.w)));
                    float s1 = fmaf(-pz[kk + 1], q.z, fmaf(-py[kk + 1], q.y, fmaf(-px[kk + 1], q.x, q.w)));
                    smin[kk]     = fminf(smin[kk],     s0);
                    smin[kk + 1] = fminf(smin[kk + 1], s1);
                    float t0 = fmaf(s0, 1.0f, hp[kk]);     // t = hp + s (FFMA-imm)
                    float t1 = fmaf(s1, 1.0f, hp[kk + 1]);
                    float tp = fminf(t0, t1);
                    tmA = (kk == 0) ? tp : fminf(tmA, tp);
                }
#pragma unroll
                for (int kk = 8; kk < 16; kk += 2) {
                    float s0 = fmaf(-pz[kk],     q.z, fmaf(-py[kk],     q.y, fmaf(-px[kk],     q.x, q.w)));
                    float s1 = fmaf(-pz[kk + 1], q.z, fmaf(-py[kk + 1], q.y, fmaf(-px[kk + 1], q.x, q.w)));
                    smin[kk]     = fminf(smin[kk],     s0);
                    smin[kk + 1] = fminf(smin[kk + 1], s1);
                    float t0 = fmaf(s0, 1.0f, hp[kk]);
                    float t1 = fmaf(s1, 1.0f, hp[kk + 1]);
                    float tp = fminf(t0, t1);
                    tmB = (kk == 8) ? tp : fminf(tmB, tp);
                }
                cm = fminf(cm, fminf(tmA, tmB));
                cm = __shfl_sync(0xffffffffu, cm, lane + 1);
            }
            scol[w][h * 32 + lane] = cm;
        }
        __syncthreads();

        // Combine 4 warps' col mins -> global atomic min.
        if (tid < JT) {
            float m = fminf(fminf(scol[0][tid], scol[1][tid]),
                            fminf(scol[2][tid], scol[3][tid]));
            atomicMin(&gcol[jch * JT + tid], __float_as_int(m));
        }
    }

    // Row flush once per CTA (add hp back here).
#pragma unroll
    for (int k = 0; k < IPT; k++)
        atomicMin(&grow[ib + k], __float_as_int(hp[k] + smin[k]));

    // Last CTA reduces everything to the scalar output.
    __threadfence();
    if (tid == 0) s_last = (atomicAdd(&g_done, 1u) == GRID - 1);
    __syncthreads();
    if (!s_last) return;
    __threadfence();

    float sum = 0.0f;
    for (int i = tid; i < NB * NPTS; i += THREADS)
        sum += __int_as_float(g_rmin[i]) + __int_as_float(g_cmin[i]);
    s_red[tid] = sum;
    __syncthreads();
    for (int o = THREADS / 2; o; o >>= 1) {
        if (tid < o) s_red[tid] += s_red[tid + o];
        __syncthreads();
    }
    // values are dist^2/2 -> x2; mean over NB batches and NPTS points.
    if (tid == 0)
        *out = s_red[0] * (2.0f / ((float)NB * (float)NPTS));
}

extern "C" void kernel_launch(void* const* d_in, const int* in_sizes, int n_in,
                              void* d_out, int out_size) {
    const float* pred = (const float*)d_in[0];
    const float* tgt  = (const float*)d_in[1];
    float* out = (float*)d_out;
    (void)in_sizes; (void)n_in; (void)out_size;

    chamfer_init_kernel<<<(NB * NPTS) / 256, 256>>>(pred, tgt);
    chamfer_cross_kernel<<<GRID, THREADS>>>(out);
}